// round 1
// baseline (speedup 1.0000x reference)
#include <cuda_runtime.h>

// GatedFusion: the reference's softmax over a singleton axis is identically 1,
// so the entire word/top-k branch is dead. Live math:
//   gate  = sigmoid([time|text] @ gate_w^T + gate_b)   (M=16384, N=896, K=1792)
//   fused = gate*time + (1-gate)*text
//   out   = fused @ out_w^T + out_b                    (M=16384, N=896, K=896)

#define BM 128
#define BN 128
#define BK 16
#define TM 8
#define TN 8
#define PAD 4
#define BMP (BM + PAD)

#define M_TOT 16384
#define D_DIM 896
#define K1    1792

// Scratch for fused activations (allocation-free rule: __device__ global).
static __device__ float g_fused[(size_t)M_TOT * D_DIM];

// ---- packed fp32x2 helpers (FFMA2 — ptxas never emits this from C++) ----
__device__ __forceinline__ void fma2(unsigned long long& acc,
                                     unsigned long long a,
                                     unsigned long long b) {
    asm("fma.rn.f32x2 %0, %1, %2, %0;" : "+l"(acc) : "l"(a), "l"(b));
}
__device__ __forceinline__ unsigned long long bcast2(float x) {
    unsigned long long r;
    asm("mov.b64 %0, {%1, %1};" : "=l"(r) : "f"(x));
    return r;
}
__device__ __forceinline__ void unpack2(float& lo, float& hi, unsigned long long v) {
    asm("mov.b64 {%0, %1}, %2;" : "=f"(lo), "=f"(hi) : "l"(v));
}

// ============================================================================
// Kernel 1: gate GEMM (K=1792, A = [time | text] virtual concat) + sigmoid fuse
// ============================================================================
__global__ void __launch_bounds__(256, 2)
k_gate_fuse(const float* __restrict__ tf, const float* __restrict__ xf,
            const float* __restrict__ gw, const float* __restrict__ gb)
{
    __shared__ float As[2][BK][BMP];
    __shared__ float Bs[2][BK][BMP];

    const int tid  = threadIdx.x;
    const int tx   = tid & 15;         // 16 thread cols
    const int ty   = tid >> 4;         // 16 thread rows
    const int m0   = blockIdx.y * BM;
    const int n0   = blockIdx.x * BN;
    const int rowL = tid >> 2;         // loader row (0..63, +64)
    const int kq   = (tid & 3) << 2;   // loader k offset {0,4,8,12}

    unsigned long long acc[TM][TN / 2];
#pragma unroll
    for (int i = 0; i < TM; i++)
#pragma unroll
        for (int j = 0; j < TN / 2; j++) acc[i][j] = 0ull;

    const int NT = K1 / BK;  // 112
    float4 ra[2], rb[2];

    // prologue: tile 0 (k in [0,16) -> time branch)
#pragma unroll
    for (int u = 0; u < 2; u++) {
        int r = rowL + u * 64;
        ra[u] = *reinterpret_cast<const float4*>(&tf[(size_t)(m0 + r) * D_DIM + kq]);
        rb[u] = *reinterpret_cast<const float4*>(&gw[(size_t)(n0 + r) * K1 + kq]);
    }
#pragma unroll
    for (int u = 0; u < 2; u++) {
        int r = rowL + u * 64;
        As[0][kq + 0][r] = ra[u].x; As[0][kq + 1][r] = ra[u].y;
        As[0][kq + 2][r] = ra[u].z; As[0][kq + 3][r] = ra[u].w;
        Bs[0][kq + 0][r] = rb[u].x; Bs[0][kq + 1][r] = rb[u].y;
        Bs[0][kq + 2][r] = rb[u].z; Bs[0][kq + 3][r] = rb[u].w;
    }
    __syncthreads();

    int cur = 0;
    for (int kt = 0; kt < NT; kt++) {
        if (kt + 1 < NT) {
            const int kb = (kt + 1) * BK;
            const float* src = (kb < D_DIM) ? tf : xf;
            const int kk = (kb < D_DIM) ? kb : kb - D_DIM;
#pragma unroll
            for (int u = 0; u < 2; u++) {
                int r = rowL + u * 64;
                ra[u] = *reinterpret_cast<const float4*>(&src[(size_t)(m0 + r) * D_DIM + kk + kq]);
                rb[u] = *reinterpret_cast<const float4*>(&gw[(size_t)(n0 + r) * K1 + kb + kq]);
            }
        }
#pragma unroll
        for (int k = 0; k < BK; k++) {
            float4 a0 = *reinterpret_cast<const float4*>(&As[cur][k][ty * TM]);
            float4 a1 = *reinterpret_cast<const float4*>(&As[cur][k][ty * TM + 4]);
            ulonglong2 b0 = *reinterpret_cast<const ulonglong2*>(&Bs[cur][k][tx * TN]);
            ulonglong2 b1 = *reinterpret_cast<const ulonglong2*>(&Bs[cur][k][tx * TN + 4]);
            float av[8] = {a0.x, a0.y, a0.z, a0.w, a1.x, a1.y, a1.z, a1.w};
            unsigned long long bv[4] = {b0.x, b0.y, b1.x, b1.y};
#pragma unroll
            for (int i = 0; i < TM; i++) {
                unsigned long long a2 = bcast2(av[i]);
#pragma unroll
                for (int j = 0; j < 4; j++) fma2(acc[i][j], a2, bv[j]);
            }
        }
        if (kt + 1 < NT) {
            const int nxt = cur ^ 1;
#pragma unroll
            for (int u = 0; u < 2; u++) {
                int r = rowL + u * 64;
                As[nxt][kq + 0][r] = ra[u].x; As[nxt][kq + 1][r] = ra[u].y;
                As[nxt][kq + 2][r] = ra[u].z; As[nxt][kq + 3][r] = ra[u].w;
                Bs[nxt][kq + 0][r] = rb[u].x; Bs[nxt][kq + 1][r] = rb[u].y;
                Bs[nxt][kq + 2][r] = rb[u].z; Bs[nxt][kq + 3][r] = rb[u].w;
            }
            __syncthreads();
            cur = nxt;
        }
    }

    // epilogue: sigmoid gate + convex blend -> g_fused
#pragma unroll
    for (int i = 0; i < TM; i++) {
        const int m = m0 + ty * TM + i;
#pragma unroll
        for (int j = 0; j < TN / 2; j++) {
            float v0, v1;
            unpack2(v0, v1, acc[i][j]);
            const int n = n0 + tx * TN + 2 * j;
            float2 gbv = *reinterpret_cast<const float2*>(&gb[n]);
            float2 tv  = *reinterpret_cast<const float2*>(&tf[(size_t)m * D_DIM + n]);
            float2 xv  = *reinterpret_cast<const float2*>(&xf[(size_t)m * D_DIM + n]);
            float g0 = 1.f / (1.f + __expf(-(v0 + gbv.x)));
            float g1 = 1.f / (1.f + __expf(-(v1 + gbv.y)));
            float2 o;
            o.x = g0 * tv.x + (1.f - g0) * xv.x;
            o.y = g1 * tv.y + (1.f - g1) * xv.y;
            *reinterpret_cast<float2*>(&g_fused[(size_t)m * D_DIM + n]) = o;
        }
    }
}

// ============================================================================
// Kernel 2: out = fused @ out_w^T + out_b   (K=896)
// ============================================================================
__global__ void __launch_bounds__(256, 2)
k_out_proj(const float* __restrict__ ow, const float* __restrict__ ob,
           float* __restrict__ out)
{
    __shared__ float As[2][BK][BMP];
    __shared__ float Bs[2][BK][BMP];

    const int tid  = threadIdx.x;
    const int tx   = tid & 15;
    const int ty   = tid >> 4;
    const int m0   = blockIdx.y * BM;
    const int n0   = blockIdx.x * BN;
    const int rowL = tid >> 2;
    const int kq   = (tid & 3) << 2;

    unsigned long long acc[TM][TN / 2];
#pragma unroll
    for (int i = 0; i < TM; i++)
#pragma unroll
        for (int j = 0; j < TN / 2; j++) acc[i][j] = 0ull;

    const int NT = D_DIM / BK;  // 56
    float4 ra[2], rb[2];

#pragma unroll
    for (int u = 0; u < 2; u++) {
        int r = rowL + u * 64;
        ra[u] = *reinterpret_cast<const float4*>(&g_fused[(size_t)(m0 + r) * D_DIM + kq]);
        rb[u] = *reinterpret_cast<const float4*>(&ow[(size_t)(n0 + r) * D_DIM + kq]);
    }
#pragma unroll
    for (int u = 0; u < 2; u++) {
        int r = rowL + u * 64;
        As[0][kq + 0][r] = ra[u].x; As[0][kq + 1][r] = ra[u].y;
        As[0][kq + 2][r] = ra[u].z; As[0][kq + 3][r] = ra[u].w;
        Bs[0][kq + 0][r] = rb[u].x; Bs[0][kq + 1][r] = rb[u].y;
        Bs[0][kq + 2][r] = rb[u].z; Bs[0][kq + 3][r] = rb[u].w;
    }
    __syncthreads();

    int cur = 0;
    for (int kt = 0; kt < NT; kt++) {
        if (kt + 1 < NT) {
            const int kb = (kt + 1) * BK;
#pragma unroll
            for (int u = 0; u < 2; u++) {
                int r = rowL + u * 64;
                ra[u] = *reinterpret_cast<const float4*>(&g_fused[(size_t)(m0 + r) * D_DIM + kb + kq]);
                rb[u] = *reinterpret_cast<const float4*>(&ow[(size_t)(n0 + r) * D_DIM + kb + kq]);
            }
        }
#pragma unroll
        for (int k = 0; k < BK; k++) {
            float4 a0 = *reinterpret_cast<const float4*>(&As[cur][k][ty * TM]);
            float4 a1 = *reinterpret_cast<const float4*>(&As[cur][k][ty * TM + 4]);
            ulonglong2 b0 = *reinterpret_cast<const ulonglong2*>(&Bs[cur][k][tx * TN]);
            ulonglong2 b1 = *reinterpret_cast<const ulonglong2*>(&Bs[cur][k][tx * TN + 4]);
            float av[8] = {a0.x, a0.y, a0.z, a0.w, a1.x, a1.y, a1.z, a1.w};
            unsigned long long bv[4] = {b0.x, b0.y, b1.x, b1.y};
#pragma unroll
            for (int i = 0; i < TM; i++) {
                unsigned long long a2 = bcast2(av[i]);
#pragma unroll
                for (int j = 0; j < 4; j++) fma2(acc[i][j], a2, bv[j]);
            }
        }
        if (kt + 1 < NT) {
            const int nxt = cur ^ 1;
#pragma unroll
            for (int u = 0; u < 2; u++) {
                int r = rowL + u * 64;
                As[nxt][kq + 0][r] = ra[u].x; As[nxt][kq + 1][r] = ra[u].y;
                As[nxt][kq + 2][r] = ra[u].z; As[nxt][kq + 3][r] = ra[u].w;
                Bs[nxt][kq + 0][r] = rb[u].x; Bs[nxt][kq + 1][r] = rb[u].y;
                Bs[nxt][kq + 2][r] = rb[u].z; Bs[nxt][kq + 3][r] = rb[u].w;
            }
            __syncthreads();
            cur = nxt;
        }
    }

#pragma unroll
    for (int i = 0; i < TM; i++) {
        const int m = m0 + ty * TM + i;
#pragma unroll
        for (int j = 0; j < TN / 2; j++) {
            float v0, v1;
            unpack2(v0, v1, acc[i][j]);
            const int n = n0 + tx * TN + 2 * j;
            float2 obv = *reinterpret_cast<const float2*>(&ob[n]);
            float2 o;
            o.x = v0 + obv.x;
            o.y = v1 + obv.y;
            *reinterpret_cast<float2*>(&out[(size_t)m * D_DIM + n]) = o;
        }
    }
}

extern "C" void kernel_launch(void* const* d_in, const int* in_sizes, int n_in,
                              void* d_out, int out_size) {
    const float* tf = (const float*)d_in[0];   // time_feat [16,1024,896]
    const float* xf = (const float*)d_in[1];   // text_feat [16,1024,896]
    // d_in[2] = word (dead code: softmax over singleton axis == 1)
    const float* gw = (const float*)d_in[3];   // gate_w [896, 1792]
    const float* gb = (const float*)d_in[4];   // gate_b [896]
    const float* ow = (const float*)d_in[5];   // out_w  [896, 896]
    const float* ob = (const float*)d_in[6];   // out_b  [896]
    float* out = (float*)d_out;                // [16,1024,896] fp32

    dim3 grid(D_DIM / BN, M_TOT / BM);  // (7, 128)
    k_gate_fuse<<<grid, 256>>>(tf, xf, gw, gb);
    k_out_proj<<<grid, 256>>>(ow, ob, out);
}

// round 3
// speedup vs baseline: 1.9319x; 1.9319x over previous
#include <cuda_runtime.h>
#include <cstdint>

// GatedFusion via mma.sync TF32 (HMMA.1688) — tcgen05 is unusable because the
// harness ptxas target is plain sm_103 (no 'a'), which rejects tcgen05.*.
// Live math (softmax over singleton axis == 1 -> word/topk branch dead):
//   gate  = sigmoid([time|text] @ gate_w^T + gate_b)   (M=16384, N=896, K=1792)
//   fused = gate*time + (1-gate)*text
//   out   = fused @ out_w^T + out_b                    (M=16384, N=896, K=896)
// All MMA operands pre-rounded with cvt.rna.tf32.f32 (RN) so tf32 truncation
// bias (~2^-10) does not accumulate.

#define M_TOT 16384
#define D_DIM 896
#define K1    1792

#define BM 128
#define BN 128
#define BK 16
#define BMP 136   // pad: bank = kq*8 + row -> conflict-free fragment LDS
#define THREADS 256

static __device__ float g_fused[(size_t)M_TOT * D_DIM];

__device__ __forceinline__ uint32_t f2tf32(float x) {
    uint32_t r; asm("cvt.rna.tf32.f32 %0, %1;" : "=r"(r) : "f"(x)); return r;
}

__device__ __forceinline__ void mma_tf32(float* c, const uint32_t* a, const uint32_t* b) {
    asm volatile(
        "mma.sync.aligned.m16n8k8.row.col.f32.tf32.tf32.f32 "
        "{%0,%1,%2,%3}, {%4,%5,%6,%7}, {%8,%9}, {%0,%1,%2,%3};"
        : "+f"(c[0]), "+f"(c[1]), "+f"(c[2]), "+f"(c[3])
        : "r"(a[0]), "r"(a[1]), "r"(a[2]), "r"(a[3]), "r"(b[0]), "r"(b[1]));
}

// ---- staging: LDG float4 -> cvt.rna.tf32 -> STS transposed [BK][BMP] --------
// 256 threads, tile 128x16: thread loads rows tid>>2 (+64), cols (tid&3)*4..+3
__device__ __forceinline__ void ldg_tile(uint4 (&r)[2], const float* src, int ld,
                                         int r0, int k0, int rowL, int kq) {
#pragma unroll
    for (int u = 0; u < 2; u++) {
        const float4 v = *reinterpret_cast<const float4*>(
            &src[(size_t)(r0 + rowL + u * 64) * ld + k0 + kq]);
        r[u] = make_uint4(f2tf32(v.x), f2tf32(v.y), f2tf32(v.z), f2tf32(v.w));
    }
}
__device__ __forceinline__ void sts_tile(uint32_t* buf, const uint4 (&r)[2],
                                         int rowL, int kq) {
#pragma unroll
    for (int u = 0; u < 2; u++) {
        const int row = rowL + u * 64;
        buf[(kq + 0) * BMP + row] = r[u].x;
        buf[(kq + 1) * BMP + row] = r[u].y;
        buf[(kq + 2) * BMP + row] = r[u].z;
        buf[(kq + 3) * BMP + row] = r[u].w;
    }
}

// ---- shared mainloop body ---------------------------------------------------
// Warp layout: 8 warps = 2 (m) x 4 (n); warp tile 64x32; per warp 4x4 mma tiles.
#define GEMM_MAINLOOP(NT, LOAD_NEXT)                                              \
    int cur = 0;                                                                  \
    for (int kt = 0; kt < (NT); kt++) {                                           \
        if (kt + 1 < (NT)) { LOAD_NEXT }                                          \
        _Pragma("unroll")                                                         \
        for (int ks = 0; ks < 2; ks++) {                                          \
            const int kq0 = ks * 8;                                               \
            uint32_t af[4][4], bf[4][2];                                          \
            _Pragma("unroll")                                                     \
            for (int mi = 0; mi < 4; mi++) {                                      \
                const int row = wm * 64 + mi * 16 + qrow;                         \
                af[mi][0] = As[cur][(kq0 + qk) * BMP + row];                      \
                af[mi][1] = As[cur][(kq0 + qk) * BMP + row + 8];                  \
                af[mi][2] = As[cur][(kq0 + qk + 4) * BMP + row];                  \
                af[mi][3] = As[cur][(kq0 + qk + 4) * BMP + row + 8];              \
            }                                                                     \
            _Pragma("unroll")                                                     \
            for (int ni = 0; ni < 4; ni++) {                                      \
                const int col = wn * 32 + ni * 8 + qrow;                          \
                bf[ni][0] = Bs[cur][(kq0 + qk) * BMP + col];                      \
                bf[ni][1] = Bs[cur][(kq0 + qk + 4) * BMP + col];                  \
            }                                                                     \
            _Pragma("unroll")                                                     \
            for (int mi = 0; mi < 4; mi++)                                        \
                _Pragma("unroll")                                                 \
                for (int ni = 0; ni < 4; ni++)                                    \
                    mma_tf32(acc[mi][ni], af[mi], bf[ni]);                        \
        }                                                                         \
        if (kt + 1 < (NT)) {                                                      \
            const int nxt = cur ^ 1;                                              \
            __syncthreads();                                                      \
            sts_tile(As[nxt], ra, rowL, kq);                                      \
            sts_tile(Bs[nxt], rb, rowL, kq);                                      \
            __syncthreads();                                                      \
            cur = nxt;                                                            \
        }                                                                         \
    }

// ============================================================================
// Kernel 1: gate GEMM (K=1792, A = [time|text] concat) + sigmoid/blend fuse
// ============================================================================
__global__ void __launch_bounds__(THREADS, 2)
k_gate_fuse(const float* __restrict__ tf, const float* __restrict__ xf,
            const float* __restrict__ gw, const float* __restrict__ gb)
{
    __shared__ uint32_t As[2][BK * BMP];
    __shared__ uint32_t Bs[2][BK * BMP];

    const int tid  = threadIdx.x;
    const int wid  = tid >> 5;
    const int lane = tid & 31;
    const int qrow = lane >> 2;
    const int qk   = lane & 3;
    const int wm   = wid & 1;
    const int wn   = wid >> 1;
    const int m0   = blockIdx.y * BM;
    const int n0   = blockIdx.x * BN;
    const int rowL = tid >> 2;
    const int kq   = (tid & 3) << 2;

    float acc[4][4][4];
#pragma unroll
    for (int mi = 0; mi < 4; mi++)
#pragma unroll
        for (int ni = 0; ni < 4; ni++)
#pragma unroll
            for (int t = 0; t < 4; t++) acc[mi][ni][t] = 0.f;

    const int NT = K1 / BK;  // 112
    uint4 ra[2], rb[2];

    ldg_tile(ra, tf, D_DIM, m0, 0, rowL, kq);
    ldg_tile(rb, gw, K1, n0, 0, rowL, kq);
    sts_tile(As[0], ra, rowL, kq);
    sts_tile(Bs[0], rb, rowL, kq);
    __syncthreads();

    GEMM_MAINLOOP(NT, {
        const int kb = (kt + 1) * BK;
        const float* srcA = (kb < D_DIM) ? tf : xf;
        const int kk = (kb < D_DIM) ? kb : kb - D_DIM;
        ldg_tile(ra, srcA, D_DIM, m0, kk, rowL, kq);
        ldg_tile(rb, gw, K1, n0, kb, rowL, kq);
    })

    // epilogue: z = acc + gb; g = sigmoid(z); fused = g*tf + (1-g)*xf
#pragma unroll
    for (int mi = 0; mi < 4; mi++) {
#pragma unroll
        for (int half = 0; half < 2; half++) {
            const int m = m0 + wm * 64 + mi * 16 + qrow + half * 8;
            const float* trow = tf + (size_t)m * D_DIM;
            const float* xrow = xf + (size_t)m * D_DIM;
            float* frow = g_fused + (size_t)m * D_DIM;
#pragma unroll
            for (int ni = 0; ni < 4; ni++) {
                const int n = n0 + wn * 32 + ni * 8 + 2 * qk;
                const float c0 = acc[mi][ni][half * 2 + 0];
                const float c1 = acc[mi][ni][half * 2 + 1];
                const float2 gbv = *reinterpret_cast<const float2*>(&gb[n]);
                const float2 tv  = *reinterpret_cast<const float2*>(&trow[n]);
                const float2 xv  = *reinterpret_cast<const float2*>(&xrow[n]);
                const float g0 = 1.f / (1.f + __expf(-(c0 + gbv.x)));
                const float g1 = 1.f / (1.f + __expf(-(c1 + gbv.y)));
                float2 o;
                o.x = g0 * tv.x + (1.f - g0) * xv.x;
                o.y = g1 * tv.y + (1.f - g1) * xv.y;
                *reinterpret_cast<float2*>(&frow[n]) = o;
            }
        }
    }
}

// ============================================================================
// Kernel 2: out = fused @ out_w^T + out_b   (K=896)
// ============================================================================
__global__ void __launch_bounds__(THREADS, 2)
k_out_proj(const float* __restrict__ ow, const float* __restrict__ ob,
           float* __restrict__ out)
{
    __shared__ uint32_t As[2][BK * BMP];
    __shared__ uint32_t Bs[2][BK * BMP];

    const int tid  = threadIdx.x;
    const int wid  = tid >> 5;
    const int lane = tid & 31;
    const int qrow = lane >> 2;
    const int qk   = lane & 3;
    const int wm   = wid & 1;
    const int wn   = wid >> 1;
    const int m0   = blockIdx.y * BM;
    const int n0   = blockIdx.x * BN;
    const int rowL = tid >> 2;
    const int kq   = (tid & 3) << 2;

    float acc[4][4][4];
#pragma unroll
    for (int mi = 0; mi < 4; mi++)
#pragma unroll
        for (int ni = 0; ni < 4; ni++)
#pragma unroll
            for (int t = 0; t < 4; t++) acc[mi][ni][t] = 0.f;

    const int NT = D_DIM / BK;  // 56
    uint4 ra[2], rb[2];

    ldg_tile(ra, g_fused, D_DIM, m0, 0, rowL, kq);
    ldg_tile(rb, ow, D_DIM, n0, 0, rowL, kq);
    sts_tile(As[0], ra, rowL, kq);
    sts_tile(Bs[0], rb, rowL, kq);
    __syncthreads();

    GEMM_MAINLOOP(NT, {
        const int kb = (kt + 1) * BK;
        ldg_tile(ra, g_fused, D_DIM, m0, kb, rowL, kq);
        ldg_tile(rb, ow, D_DIM, n0, kb, rowL, kq);
    })

#pragma unroll
    for (int mi = 0; mi < 4; mi++) {
#pragma unroll
        for (int half = 0; half < 2; half++) {
            const int m = m0 + wm * 64 + mi * 16 + qrow + half * 8;
            float* orow = out + (size_t)m * D_DIM;
#pragma unroll
            for (int ni = 0; ni < 4; ni++) {
                const int n = n0 + wn * 32 + ni * 8 + 2 * qk;
                const float2 obv = *reinterpret_cast<const float2*>(&ob[n]);
                float2 o;
                o.x = acc[mi][ni][half * 2 + 0] + obv.x;
                o.y = acc[mi][ni][half * 2 + 1] + obv.y;
                *reinterpret_cast<float2*>(&orow[n]) = o;
            }
        }
    }
}

extern "C" void kernel_launch(void* const* d_in, const int* in_sizes, int n_in,
                              void* d_out, int out_size) {
    const float* tf = (const float*)d_in[0];   // time_feat [16,1024,896]
    const float* xf = (const float*)d_in[1];   // text_feat [16,1024,896]
    // d_in[2] = word (dead: softmax over singleton axis == 1)
    const float* gw = (const float*)d_in[3];   // gate_w [896, 1792]
    const float* gb = (const float*)d_in[4];   // gate_b [896]
    const float* ow = (const float*)d_in[5];   // out_w  [896, 896]
    const float* ob = (const float*)d_in[6];   // out_b  [896]
    float* out = (float*)d_out;                // [16,1024,896] fp32

    dim3 grid(D_DIM / BN, M_TOT / BM);  // (7, 128)
    k_gate_fuse<<<grid, THREADS>>>(tf, xf, gw, gb);
    k_out_proj<<<grid, THREADS>>>(ow, ob, out);
}

// round 5
// speedup vs baseline: 4.8675x; 2.5196x over previous
#include <cuda_runtime.h>
#include <cuda_fp16.h>
#include <cstdint>

// GatedFusion via mma.sync f16 (m16n8k16, fp32 accum).
// Live math (softmax over singleton axis == 1 -> word/topk branch dead):
//   gate  = sigmoid([time|text] @ gate_w^T + gate_b)   (M=16384, N=896, K=1792)
//   fused = gate*time + (1-gate)*text
//   out   = fused @ out_w^T + out_b                    (M=16384, N=896, K=896)
// fp16 carries the same 11-bit significand as tf32 (R3: rel_err 3.15e-4), but
// halves all operand bytes and doubles K per MMA. Inputs/weights pre-converted
// to half once; blend epilogue still reads fp32 originals.

#define M_TOT 16384
#define D_DIM 896
#define K1    1792

#define BM 128
#define BN 128
#define BK 32
#define THREADS 256

static __device__ __half g_tf_h[(size_t)M_TOT * D_DIM];
static __device__ __half g_xf_h[(size_t)M_TOT * D_DIM];
static __device__ __half g_gw_h[(size_t)D_DIM * K1];
static __device__ __half g_ow_h[(size_t)D_DIM * D_DIM];
static __device__ __half g_fused[(size_t)M_TOT * D_DIM];

// ---------------- small helpers ---------------------------------------------
__device__ __forceinline__ void ldm_x4(uint32_t* r, uint32_t addr) {
    asm volatile("ldmatrix.sync.aligned.m8n8.x4.shared.b16 {%0,%1,%2,%3}, [%4];"
                 : "=r"(r[0]), "=r"(r[1]), "=r"(r[2]), "=r"(r[3]) : "r"(addr));
}
__device__ __forceinline__ void mma_f16(float* c, const uint32_t* a, const uint32_t* b) {
    asm volatile(
        "mma.sync.aligned.m16n8k16.row.col.f32.f16.f16.f32 "
        "{%0,%1,%2,%3}, {%4,%5,%6,%7}, {%8,%9}, {%0,%1,%2,%3};"
        : "+f"(c[0]), "+f"(c[1]), "+f"(c[2]), "+f"(c[3])
        : "r"(a[0]), "r"(a[1]), "r"(a[2]), "r"(a[3]), "r"(b[0]), "r"(b[1]));
}

// ---------------- fp32 -> fp16 pre-convert ----------------------------------
__global__ void k_f2h(const float* __restrict__ src, __half* __restrict__ dst, int n) {
    int i = (blockIdx.x * blockDim.x + threadIdx.x) * 4;
    if (i < n) {
        float4 v = *reinterpret_cast<const float4*>(&src[i]);
        __half2 hh[2];
        hh[0] = __floats2half2_rn(v.x, v.y);
        hh[1] = __floats2half2_rn(v.z, v.w);
        *reinterpret_cast<uint2*>(&dst[i]) = *reinterpret_cast<uint2*>(hh);
    }
}

// ---------------- staging: LDG.128 half -> swizzled STS.128 ------------------
// Tile = 128 rows x 32 k (half). Shared layout: 16B entries, entry(slab,row) =
// slab*128 + (row ^ (slab*2)), slab = k8/8 in {0..3}. XOR swizzle makes both
// STS.128 staging and ldmatrix row-gathers bank-conflict-free.
__device__ __forceinline__ void ldg_h(uint4 (&r)[2], const __half* __restrict__ src,
                                      int ld, int r0, int k0, int rowL, int k8) {
#pragma unroll
    for (int u = 0; u < 2; u++)
        r[u] = *reinterpret_cast<const uint4*>(
            &src[(size_t)(r0 + rowL + u * 64) * ld + k0 + k8]);
}
__device__ __forceinline__ void sts_h(uint4* buf, const uint4 (&r)[2], int rowL, int k8) {
    const int slab = k8 >> 3;
#pragma unroll
    for (int u = 0; u < 2; u++) {
        const int row = rowL + u * 64;
        buf[slab * 128 + (row ^ (slab * 2))] = r[u];
    }
}

// ---------------- mainloop ---------------------------------------------------
// 8 warps = 2(m) x 4(n); warp tile 64x32; per warp: mi=4, ni=4, mma m16n8k16.
#define GEMM_MAINLOOP(NT, LOAD_NEXT)                                              \
    int cur = 0;                                                                  \
    for (int kt = 0; kt < (NT); kt++) {                                           \
        if (kt + 1 < (NT)) { LOAD_NEXT }                                          \
        _Pragma("unroll")                                                         \
        for (int ks = 0; ks < 2; ks++) {                                          \
            uint32_t af[4][4], bf[4][2];                                          \
            _Pragma("unroll")                                                     \
            for (int mi = 0; mi < 4; mi++) {                                      \
                const int slab = ks * 2 + a_kh;                                   \
                const int row = wm * 64 + mi * 16 + a_row;                        \
                ldm_x4(af[mi], abase +                                            \
                       (uint32_t)(cur * 512 + slab * 128 + (row ^ (slab * 2))) * 16); \
            }                                                                     \
            _Pragma("unroll")                                                     \
            for (int np = 0; np < 2; np++) {                                      \
                const int slab = ks * 2 + b_kh;                                   \
                const int nrow = wn * 32 + np * 16 + b_row;                       \
                uint32_t t[4];                                                    \
                ldm_x4(t, bbase +                                                 \
                       (uint32_t)(cur * 512 + slab * 128 + (nrow ^ (slab * 2))) * 16); \
                bf[np * 2][0] = t[0]; bf[np * 2][1] = t[1];                       \
                bf[np * 2 + 1][0] = t[2]; bf[np * 2 + 1][1] = t[3];               \
            }                                                                     \
            _Pragma("unroll")                                                     \
            for (int mi = 0; mi < 4; mi++)                                        \
                _Pragma("unroll")                                                 \
                for (int ni = 0; ni < 4; ni++)                                    \
                    mma_f16(acc[mi][ni], af[mi], bf[ni]);                         \
        }                                                                         \
        if (kt + 1 < (NT)) {                                                      \
            const int nxt = cur ^ 1;                                              \
            __syncthreads();                                                      \
            sts_h(As + nxt * 512, ra, rowL, k8);                                  \
            sts_h(Bs + nxt * 512, rb, rowL, k8);                                  \
            __syncthreads();                                                      \
            cur = nxt;                                                            \
        }                                                                         \
    }

#define GEMM_PREAMBLE                                                             \
    const int tid  = threadIdx.x;                                                 \
    const int wid  = tid >> 5;                                                    \
    const int lane = tid & 31;                                                    \
    const int qrow = lane >> 2;                                                   \
    const int qk   = lane & 3;                                                    \
    const int wm   = wid & 1;                                                     \
    const int wn   = wid >> 1;                                                    \
    const int m0   = blockIdx.y * BM;                                             \
    const int n0   = blockIdx.x * BN;                                             \
    const int rowL = tid >> 2;                                                    \
    const int k8   = (tid & 3) * 8;                                               \
    const int a_row = lane & 15;                                                  \
    const int a_kh  = lane >> 4;                                                  \
    const int b_row = (lane & 7) + ((lane >> 4) << 3);                            \
    const int b_kh  = (lane >> 3) & 1;                                            \
    const uint32_t abase = (uint32_t)__cvta_generic_to_shared(As);                 \
    const uint32_t bbase = (uint32_t)__cvta_generic_to_shared(Bs);                 \
    float acc[4][4][4];                                                           \
    _Pragma("unroll")                                                             \
    for (int mi = 0; mi < 4; mi++)                                                \
        _Pragma("unroll")                                                         \
        for (int ni = 0; ni < 4; ni++)                                            \
            _Pragma("unroll")                                                     \
            for (int t = 0; t < 4; t++) acc[mi][ni][t] = 0.f;

// ============================================================================
// Kernel 1: gate GEMM (K=1792, A = [time|text] concat) + sigmoid/blend fuse
// ============================================================================
__global__ void __launch_bounds__(THREADS, 2)
k_gate_fuse(const float* __restrict__ tf, const float* __restrict__ xf,
            const float* __restrict__ gb)
{
    __shared__ uint4 As[1024];
    __shared__ uint4 Bs[1024];
    GEMM_PREAMBLE

    const int NT = K1 / BK;  // 56
    uint4 ra[2], rb[2];

    ldg_h(ra, g_tf_h, D_DIM, m0, 0, rowL, k8);
    ldg_h(rb, g_gw_h, K1, n0, 0, rowL, k8);
    sts_h(As, ra, rowL, k8);
    sts_h(Bs, rb, rowL, k8);
    __syncthreads();

    GEMM_MAINLOOP(NT, {
        const int kb = (kt + 1) * BK;
        const __half* srcA = (kb < D_DIM) ? g_tf_h : g_xf_h;
        const int kk = (kb < D_DIM) ? kb : kb - D_DIM;
        ldg_h(ra, srcA, D_DIM, m0, kk, rowL, k8);
        ldg_h(rb, g_gw_h, K1, n0, kb, rowL, k8);
    })

    // epilogue: z = acc + gb; g = sigmoid(z); fused = g*tf + (1-g)*xf (fp32 blend)
#pragma unroll
    for (int mi = 0; mi < 4; mi++) {
#pragma unroll
        for (int half = 0; half < 2; half++) {
            const int m = m0 + wm * 64 + mi * 16 + qrow + half * 8;
            const float* trow = tf + (size_t)m * D_DIM;
            const float* xrow = xf + (size_t)m * D_DIM;
            __half* frow = g_fused + (size_t)m * D_DIM;
#pragma unroll
            for (int ni = 0; ni < 4; ni++) {
                const int n = n0 + wn * 32 + ni * 8 + 2 * qk;
                const float c0 = acc[mi][ni][half * 2 + 0];
                const float c1 = acc[mi][ni][half * 2 + 1];
                const float2 gbv = *reinterpret_cast<const float2*>(&gb[n]);
                const float2 tv  = *reinterpret_cast<const float2*>(&trow[n]);
                const float2 xv  = *reinterpret_cast<const float2*>(&xrow[n]);
                const float g0 = 1.f / (1.f + __expf(-(c0 + gbv.x)));
                const float g1 = 1.f / (1.f + __expf(-(c1 + gbv.y)));
                const float f0 = g0 * tv.x + (1.f - g0) * xv.x;
                const float f1 = g1 * tv.y + (1.f - g1) * xv.y;
                *reinterpret_cast<__half2*>(&frow[n]) = __floats2half2_rn(f0, f1);
            }
        }
    }
}

// ============================================================================
// Kernel 2: out = fused @ out_w^T + out_b   (K=896)
// ============================================================================
__global__ void __launch_bounds__(THREADS, 2)
k_out_proj(const float* __restrict__ ob, float* __restrict__ out)
{
    __shared__ uint4 As[1024];
    __shared__ uint4 Bs[1024];
    GEMM_PREAMBLE

    const int NT = D_DIM / BK;  // 28
    uint4 ra[2], rb[2];

    ldg_h(ra, g_fused, D_DIM, m0, 0, rowL, k8);
    ldg_h(rb, g_ow_h, D_DIM, n0, 0, rowL, k8);
    sts_h(As, ra, rowL, k8);
    sts_h(Bs, rb, rowL, k8);
    __syncthreads();

    GEMM_MAINLOOP(NT, {
        const int kb = (kt + 1) * BK;
        ldg_h(ra, g_fused, D_DIM, m0, kb, rowL, k8);
        ldg_h(rb, g_ow_h, D_DIM, n0, kb, rowL, k8);
    })

#pragma unroll
    for (int mi = 0; mi < 4; mi++) {
#pragma unroll
        for (int half = 0; half < 2; half++) {
            const int m = m0 + wm * 64 + mi * 16 + qrow + half * 8;
            float* orow = out + (size_t)m * D_DIM;
#pragma unroll
            for (int ni = 0; ni < 4; ni++) {
                const int n = n0 + wn * 32 + ni * 8 + 2 * qk;
                const float2 obv = *reinterpret_cast<const float2*>(&ob[n]);
                float2 o;
                o.x = acc[mi][ni][half * 2 + 0] + obv.x;
                o.y = acc[mi][ni][half * 2 + 1] + obv.y;
                *reinterpret_cast<float2*>(&orow[n]) = o;
            }
        }
    }
}

extern "C" void kernel_launch(void* const* d_in, const int* in_sizes, int n_in,
                              void* d_out, int out_size) {
    const float* tf = (const float*)d_in[0];   // time_feat [16,1024,896]
    const float* xf = (const float*)d_in[1];   // text_feat [16,1024,896]
    // d_in[2] = word (dead: softmax over singleton axis == 1)
    const float* gw = (const float*)d_in[3];   // gate_w [896, 1792]
    const float* gb = (const float*)d_in[4];   // gate_b [896]
    const float* ow = (const float*)d_in[5];   // out_w  [896, 896]
    const float* ob = (const float*)d_in[6];   // out_b  [896]
    float* out = (float*)d_out;                // [16,1024,896] fp32

    const int n_act = M_TOT * D_DIM;      // 14,680,064
    const int n_gw  = D_DIM * K1;         // 1,605,632
    const int n_ow  = D_DIM * D_DIM;      // 802,816

    __half* tf_h; cudaGetSymbolAddress((void**)&tf_h, g_tf_h);
    __half* xf_h; cudaGetSymbolAddress((void**)&xf_h, g_xf_h);
    __half* gw_h; cudaGetSymbolAddress((void**)&gw_h, g_gw_h);
    __half* ow_h; cudaGetSymbolAddress((void**)&ow_h, g_ow_h);

    k_f2h<<<(n_act / 4 + 255) / 256, 256>>>(tf, tf_h, n_act);
    k_f2h<<<(n_act / 4 + 255) / 256, 256>>>(xf, xf_h, n_act);
    k_f2h<<<(n_gw  / 4 + 255) / 256, 256>>>(gw, gw_h, n_gw);
    k_f2h<<<(n_ow  / 4 + 255) / 256, 256>>>(ow, ow_h, n_ow);

    dim3 grid(D_DIM / BN, M_TOT / BM);  // (7, 128)
    k_gate_fuse<<<grid, THREADS>>>(tf, xf, gb);
    k_out_proj<<<grid, THREADS>>>(ob, out);
}